// round 2
// baseline (speedup 1.0000x reference)
#include <cuda_runtime.h>

#define N_IN    8192
#define K_SEL   256
#define THREADS 1024
#define EPT     8
#define WARPS   32

__device__ __forceinline__ unsigned f2key(float x) {
    unsigned u = __float_as_uint(x);
    // order-preserving map: larger float -> larger unsigned
    return (u & 0x80000000u) ? ~u : (u | 0x80000000u);
}

// Descending-cumulative scan over 256-bin histogram (warp 0 only).
// Finds digit where cumulative-from-top crosses *s_kr; updates *s_kr to the
// residual rank within that digit class and writes *s_digit.
__device__ __forceinline__ void desc_scan_256(const unsigned* __restrict__ hist,
                                              int t, int lane,
                                              int* s_kr, int* s_digit) {
    if (t < 32) {
        const int hi = 255 - 8 * t;           // lane covers digits [hi-7 .. hi] descending
        int h[8];
        int sum = 0;
        #pragma unroll
        for (int j = 0; j < 8; j++) { h[j] = (int)hist[hi - j]; sum += h[j]; }
        int v = sum;
        #pragma unroll
        for (int off = 1; off < 32; off *= 2) {
            int n = __shfl_up_sync(0xFFFFFFFFu, v, off);
            if (lane >= off) v += n;
        }
        const int excl = v - sum;             // count strictly above this lane's chunk
        const int krr = *s_kr;
        __syncwarp();                         // all lanes read krr before unique write
        if (excl < krr && excl + sum >= krr) {
            int acc = excl;
            #pragma unroll
            for (int j = 0; j < 8; j++) {
                if (acc + h[j] >= krr) { *s_digit = hi - j; *s_kr = krr - acc; break; }
                acc += h[j];
            }
        }
    }
}

__global__ __launch_bounds__(THREADS, 1)
void topk_hard_kernel(const float* __restrict__ logits,
                      const float* __restrict__ noise,
                      const float* __restrict__ smem_in,
                      float* __restrict__ out)
{
    __shared__ unsigned whist[WARPS * 256];   // 32KB: per-warp hists, later cand[] buffer
    __shared__ unsigned combined[256];
    __shared__ int      warp_sums[WARPS];
    __shared__ int      s_kr, s_digit, s_cnt;
    __shared__ unsigned s_thrKey;
    __shared__ int      s_r, s_e;

    const int b    = blockIdx.x;
    const int t    = threadIdx.x;
    const int lane = t & 31;
    const int wid  = t >> 5;
    const int base = t * EPT;

    const float* L = logits  + (size_t)b * N_IN;
    const float* G = noise   + (size_t)b * N_IN;
    const float* M = smem_in + (size_t)b * N_IN;
    float*       O = out     + (size_t)b * N_IN;

    // ---- load: contiguous EPT floats per thread (2x float4 per array)
    float mem[EPT];
    unsigned key[EPT];
    {
        float4 l0 = *reinterpret_cast<const float4*>(L + base);
        float4 l1 = *reinterpret_cast<const float4*>(L + base + 4);
        float4 g0 = *reinterpret_cast<const float4*>(G + base);
        float4 g1 = *reinterpret_cast<const float4*>(G + base + 4);
        float4 m0 = *reinterpret_cast<const float4*>(M + base);
        float4 m1 = *reinterpret_cast<const float4*>(M + base + 4);
        float lv[EPT] = {l0.x,l0.y,l0.z,l0.w,l1.x,l1.y,l1.z,l1.w};
        float gv[EPT] = {g0.x,g0.y,g0.z,g0.w,g1.x,g1.y,g1.z,g1.w};
        float mv[EPT] = {m0.x,m0.y,m0.z,m0.w,m1.x,m1.y,m1.z,m1.w};
        #pragma unroll
        for (int j = 0; j < EPT; j++) {
            mem[j] = mv[j];
            float p = (lv[j] + gv[j]) + mv[j] * (-1000.0f);
            key[j] = f2key(p);
        }
    }

    // ---- zero per-warp hists (8192 words -> 2 uint4 stores/thread)
    const uint4 z4 = make_uint4(0u, 0u, 0u, 0u);
    reinterpret_cast<uint4*>(whist)[t]           = z4;
    reinterpret_cast<uint4*>(whist)[t + THREADS] = z4;
    if (t == 0) { s_kr = K_SEL; s_cnt = 0; }
    __syncthreads();

    unsigned* wh = whist + wid * 256;

    // ---- pass 1: 8-bit digit (bits 31:24), per-warp non-atomic RMW histogram.
    // match_any_sync both aggregates same-digit lanes (leader writes popc) and
    // orders the RMWs between iterations (it is a warp sync).
    #pragma unroll
    for (int j = 0; j < EPT; j++) {
        unsigned d  = key[j] >> 24;
        unsigned mm = __match_any_sync(0xFFFFFFFFu, d);
        if ((int)(__ffs(mm) - 1) == lane) wh[d] += __popc(mm);
    }
    __syncthreads();

    // cross-warp reduce into combined[256]
    if (t < 256) {
        unsigned s = 0;
        #pragma unroll
        for (int w = 0; w < WARPS; w++) s += whist[w * 256 + t];
        combined[t] = s;
    }
    __syncthreads();

    desc_scan_256(combined, t, lane, &s_kr, &s_digit);
    __syncthreads();

    const unsigned d1 = (unsigned)s_digit;
    const int m1 = (int)combined[d1];
    unsigned prefix, shiftv;

    if (m1 > 128) {
        // ---- pass 2: bits 23:16 restricted to pass-1 bucket
        reinterpret_cast<uint4*>(whist)[t]           = z4;
        reinterpret_cast<uint4*>(whist)[t + THREADS] = z4;
        __syncthreads();

        #pragma unroll
        for (int j = 0; j < EPT; j++) {
            bool p = ((key[j] >> 24) == d1);
            unsigned act = __ballot_sync(0xFFFFFFFFu, p);
            if (p) {
                unsigned d  = (key[j] >> 16) & 0xFFu;
                unsigned mm = __match_any_sync(act, d);
                if ((int)(__ffs(mm) - 1) == lane) wh[d] += __popc(mm);
            }
        }
        __syncthreads();

        if (t < 256) {
            unsigned s = 0;
            #pragma unroll
            for (int w = 0; w < WARPS; w++) s += whist[w * 256 + t];
            combined[t] = s;
        }
        __syncthreads();

        desc_scan_256(combined, t, lane, &s_kr, &s_digit);
        __syncthreads();

        prefix = (d1 << 8) | (unsigned)s_digit;
        shiftv = 16u;
    } else {
        prefix = d1;
        shiftv = 24u;
    }

    // ---- candidate gather (reuse whist storage as cand[], up to 8192 keys)
    unsigned* cand = whist;
    #pragma unroll
    for (int j = 0; j < EPT; j++) {
        if ((key[j] >> shiftv) == prefix) {
            int pos = atomicAdd(&s_cnt, 1);
            cand[pos] = key[j];
        }
    }
    __syncthreads();

    const int m   = s_cnt;
    const int krr = s_kr;

    // ---- exact rank among candidates: O(m^2) over 1024 threads (m typically ~4-64)
    for (int idx = t; idx < m; idx += THREADS) {
        const unsigned c = cand[idx];
        int g = 0, e = 0;
        for (int i = 0; i < m; i++) {
            unsigned v = cand[i];   // broadcast read
            g += (v > c);
            e += (v == c);
        }
        if (g < krr && krr <= g + e) {   // c is the K-th largest key
            s_thrKey = c;
            s_r      = krr - g;          // take r of the e equal keys (by index order)
            s_e      = e;
        }
    }
    __syncthreads();

    const unsigned thrKey = s_thrKey;
    float o[EPT];

    if (s_e == 1) {
        // threshold key unique (typical): simple compare
        #pragma unroll
        for (int j = 0; j < EPT; j++)
            o[j] = mem[j] + ((key[j] >= thrKey) ? 1.0f : 0.0f);
    } else {
        // exact-duplicate threshold keys: index-ordered tie-break via block scan
        const int r = s_r;
        int local = 0;
        #pragma unroll
        for (int j = 0; j < EPT; j++) local += (key[j] == thrKey);

        int incl = local;
        #pragma unroll
        for (int off = 1; off < 32; off *= 2) {
            int n = __shfl_up_sync(0xFFFFFFFFu, incl, off);
            if (lane >= off) incl += n;
        }
        if (lane == 31) warp_sums[wid] = incl;
        __syncthreads();
        if (t < 32) {
            int v2 = warp_sums[t];
            int i2 = v2;
            #pragma unroll
            for (int off = 1; off < 32; off *= 2) {
                int n = __shfl_up_sync(0xFFFFFFFFu, i2, off);
                if (t >= off) i2 += n;
            }
            warp_sums[t] = i2 - v2;   // exclusive
        }
        __syncthreads();

        int rank = warp_sums[wid] + (incl - local);
        #pragma unroll
        for (int j = 0; j < EPT; j++) {
            bool sel;
            if (key[j] > thrKey)       sel = true;
            else if (key[j] == thrKey) { sel = (rank < r); rank++; }
            else                       sel = false;
            o[j] = mem[j] + (sel ? 1.0f : 0.0f);
        }
    }

    *reinterpret_cast<float4*>(O + base)     = make_float4(o[0], o[1], o[2], o[3]);
    *reinterpret_cast<float4*>(O + base + 4) = make_float4(o[4], o[5], o[6], o[7]);
}

extern "C" void kernel_launch(void* const* d_in, const int* in_sizes, int n_in,
                              void* d_out, int out_size) {
    const float* logits = (const float*)d_in[0];
    const float* noise  = (const float*)d_in[1];
    const float* smem   = (const float*)d_in[2];
    float* out = (float*)d_out;

    const int B = in_sizes[0] / N_IN;
    topk_hard_kernel<<<B, THREADS>>>(logits, noise, smem, out);
}